// round 1
// baseline (speedup 1.0000x reference)
#include <cuda_runtime.h>
#include <math.h>

#define NHALF 8192
#define NTOT  16384
#define DIMK  128

// Scratch accumulators (allocation-free rule: __device__ globals)
__device__ float g_norm[NTOT];
__device__ float g_rowsum_aa[NHALF];
__device__ float g_rowsum_bb[NHALF];
__device__ float g_rowsum_ab[NHALF];
__device__ float g_colsum_ab[NHALF];
__device__ float g_diaglog;

__global__ void zero_kernel() {
    int i = blockIdx.x * blockDim.x + threadIdx.x;
    if (i < NHALF) {
        g_rowsum_aa[i] = 0.f;
        g_rowsum_bb[i] = 0.f;
        g_rowsum_ab[i] = 0.f;
        g_colsum_ab[i] = 0.f;
    }
    if (i == 0) g_diaglog = 0.f;
}

// One warp per row: 128 floats = 32 float4, one per lane.
__global__ void norm_kernel(const float* __restrict__ F) {
    int gw = (blockIdx.x * blockDim.x + threadIdx.x) >> 5;
    int lane = threadIdx.x & 31;
    if (gw >= NTOT) return;
    const float4* p = reinterpret_cast<const float4*>(F + (size_t)gw * DIMK);
    float4 v = p[lane];
    float s = v.x * v.x + v.y * v.y + v.z * v.z + v.w * v.w;
    #pragma unroll
    for (int o = 16; o > 0; o >>= 1) s += __shfl_xor_sync(0xffffffffu, s, o);
    if (lane == 0) g_norm[gw] = s;
}

// Tile kernel: 128x128 output tile, 256 threads, 8x8 micro-tile each.
// blockIdx.z: quadrant q (0 = aa, 1 = bb, 2 = ab). For q<2 only upper
// triangle tiles (tj >= ti) are computed; off-diagonal tiles scatter
// symmetric contributions to both row sets.
__global__ void __launch_bounds__(256) pair_kernel(const float* __restrict__ F) {
    int q  = blockIdx.z;
    int ti = blockIdx.y;
    int tj = blockIdx.x;
    if (q < 2 && tj < ti) return;

    int rowBase = (q == 1) ? NHALF : 0;
    int colBase = (q == 0) ? 0 : NHALF;
    int iBase = rowBase + ti * 128;
    int jBase = colBase + tj * 128;

    __shared__ float As[32][128];   // k-major: As[k][row]
    __shared__ float Bs[32][128];

    int tid = threadIdx.x;
    int tx = tid & 15;       // col group
    int ty = tid >> 4;       // row group
    int row  = tid & 127;    // load row
    int half = tid >> 7;     // 0/1 selects k slot parity

    float acc[8][8];
    #pragma unroll
    for (int u = 0; u < 8; u++)
        #pragma unroll
        for (int v = 0; v < 8; v++) acc[u][v] = 0.f;

    for (int kc = 0; kc < DIMK; kc += 32) {
        // Load 128x32 tiles of A and B, transposed to k-major in smem.
        #pragma unroll
        for (int t = 0; t < 4; t++) {
            int k = (t * 2 + half) * 4;
            float4 a = *reinterpret_cast<const float4*>(
                F + (size_t)(iBase + row) * DIMK + kc + k);
            As[k + 0][row] = a.x; As[k + 1][row] = a.y;
            As[k + 2][row] = a.z; As[k + 3][row] = a.w;
            float4 b = *reinterpret_cast<const float4*>(
                F + (size_t)(jBase + row) * DIMK + kc + k);
            Bs[k + 0][row] = b.x; Bs[k + 1][row] = b.y;
            Bs[k + 2][row] = b.z; Bs[k + 3][row] = b.w;
        }
        __syncthreads();

        #pragma unroll
        for (int k = 0; k < 32; k++) {
            float ra[8], rb[8];
            float4 a0 = *reinterpret_cast<float4*>(&As[k][ty * 8]);
            float4 a1 = *reinterpret_cast<float4*>(&As[k][ty * 8 + 4]);
            float4 b0 = *reinterpret_cast<float4*>(&Bs[k][tx * 8]);
            float4 b1 = *reinterpret_cast<float4*>(&Bs[k][tx * 8 + 4]);
            ra[0] = a0.x; ra[1] = a0.y; ra[2] = a0.z; ra[3] = a0.w;
            ra[4] = a1.x; ra[5] = a1.y; ra[6] = a1.z; ra[7] = a1.w;
            rb[0] = b0.x; rb[1] = b0.y; rb[2] = b0.z; rb[3] = b0.w;
            rb[4] = b1.x; rb[5] = b1.y; rb[6] = b1.z; rb[7] = b1.w;
            #pragma unroll
            for (int u = 0; u < 8; u++)
                #pragma unroll
                for (int v = 0; v < 8; v++)
                    acc[u][v] = fmaf(ra[u], rb[v], acc[u][v]);
        }
        __syncthreads();
    }

    // Epilogue: dot -> Cauchy sim, accumulate row/col partial sums.
    float ni[8], nj[8];
    #pragma unroll
    for (int u = 0; u < 8; u++) ni[u] = g_norm[iBase + ty * 8 + u];
    #pragma unroll
    for (int v = 0; v < 8; v++) nj[v] = g_norm[jBase + tx * 8 + v];

    float rs[8], cs[8];
    #pragma unroll
    for (int u = 0; u < 8; u++) { rs[u] = 0.f; cs[u] = 0.f; }

    bool diagTile = (ti == tj);
    float dlog = 0.f;

    #pragma unroll
    for (int u = 0; u < 8; u++) {
        #pragma unroll
        for (int v = 0; v < 8; v++) {
            float d2 = fmaxf(ni[u] + nj[v] - 2.f * acc[u][v], 0.f);
            float sim = __fdividef(1.f, d2 + 1.f);
            if (diagTile && (ty * 8 + u) == (tx * 8 + v)) {
                if (q < 2) sim = 0.f;           // zero diag of aa / bb
                else       dlog += logf(sim);    // alignment term (ab diag)
            }
            rs[u] += sim;
            cs[v] += sim;
        }
    }
    if (q == 2 && diagTile && tx == ty) atomicAdd(&g_diaglog, dlog);

    // Reduce partial sums across the block (reuse smem).
    float* red  = &As[0][0];   // [128][16] row partials
    float* cred = &Bs[0][0];   // [128][16] col partials
    #pragma unroll
    for (int u = 0; u < 8; u++) red[(ty * 8 + u) * 16 + tx] = rs[u];
    #pragma unroll
    for (int v = 0; v < 8; v++) cred[(tx * 8 + v) * 16 + ty] = cs[v];
    __syncthreads();

    if (tid < 128) {
        float s = 0.f;
        #pragma unroll
        for (int t = 0; t < 16; t++) s += red[tid * 16 + t];
        int i = ti * 128 + tid;
        if (q == 0)      atomicAdd(&g_rowsum_aa[i], s);
        else if (q == 1) atomicAdd(&g_rowsum_bb[i], s);
        else             atomicAdd(&g_rowsum_ab[i], s);
    } else {
        int c = tid - 128;
        float s = 0.f;
        #pragma unroll
        for (int t = 0; t < 16; t++) s += cred[c * 16 + t];
        int j = tj * 128 + c;
        if (q == 2) {
            atomicAdd(&g_colsum_ab[j], s);
        } else if (ti != tj) {   // symmetric mirror contribution
            if (q == 0) atomicAdd(&g_rowsum_aa[j], s);
            else        atomicAdd(&g_rowsum_bb[j], s);
        }
    }
}

__global__ void finalize_kernel(float* __restrict__ out) {
    __shared__ float sh[256];
    float s = 0.f;
    for (int j = threadIdx.x; j < NHALF; j += 256) {
        s += logf(g_colsum_ab[j] + g_rowsum_bb[j]);   // logsumexp_1 terms
        s += logf(g_rowsum_aa[j] + g_rowsum_ab[j]);   // logsumexp_2 terms
    }
    sh[threadIdx.x] = s;
    __syncthreads();
    for (int o = 128; o > 0; o >>= 1) {
        if (threadIdx.x < o) sh[threadIdx.x] += sh[threadIdx.x + o];
        __syncthreads();
    }
    if (threadIdx.x == 0) {
        float raw_uniformity = sh[0] / (float)NHALF;        // ls1 + ls2
        float alignment = g_diaglog / (float)NHALF;
        out[0] = -(alignment - 0.5f * raw_uniformity);
    }
}

extern "C" void kernel_launch(void* const* d_in, const int* in_sizes, int n_in,
                              void* d_out, int out_size) {
    const float* F = (const float*)d_in[0];
    float* out = (float*)d_out;

    zero_kernel<<<(NHALF + 255) / 256, 256>>>();
    norm_kernel<<<(NTOT * 32) / 256, 256>>>(F);
    dim3 grid(64, 64, 3);
    pair_kernel<<<grid, 256>>>(F);
    finalize_kernel<<<1, 256>>>(out);
}

// round 3
// speedup vs baseline: 2.8179x; 2.8179x over previous
#include <cuda_runtime.h>
#include <math.h>
#include <stdint.h>

#define NHALF 8192
#define NTOT  16384
#define DIMK  128

// ---------------- device scratch (allocation-free rule) ----------------
__device__ float g_norm[NTOT];
__device__ float g_rowsum_aa[NHALF];
__device__ float g_rowsum_bb[NHALF];
__device__ float g_rowsum_ab[NHALF];
__device__ float g_colsum_ab[NHALF];
__device__ float g_alignneg;   // sum_i log(1 + |a_i - b_i|^2)  (exact fp32)

__device__ __forceinline__ uint32_t s2u(const void* p) {
    uint32_t r;
    asm("{ .reg .u64 t; cvta.to.shared.u64 t, %1; cvt.u32.u64 %0, t; }"
        : "=r"(r) : "l"(p));
    return r;
}

__device__ __forceinline__ void mma_tf32(float* d, const uint32_t* a, const uint32_t* b) {
    asm volatile(
        "mma.sync.aligned.m16n8k8.row.col.f32.tf32.tf32.f32 "
        "{%0,%1,%2,%3}, {%4,%5,%6,%7}, {%8,%9}, {%0,%1,%2,%3};"
        : "+f"(d[0]), "+f"(d[1]), "+f"(d[2]), "+f"(d[3])
        : "r"(a[0]), "r"(a[1]), "r"(a[2]), "r"(a[3]), "r"(b[0]), "r"(b[1]));
}

// ---------------- trivial kernels ----------------
__global__ void zero_kernel() {
    int i = blockIdx.x * blockDim.x + threadIdx.x;
    if (i < NHALF) {
        g_rowsum_aa[i] = 0.f; g_rowsum_bb[i] = 0.f;
        g_rowsum_ab[i] = 0.f; g_colsum_ab[i] = 0.f;
    }
    if (i == 0) g_alignneg = 0.f;
}

__global__ void norm_kernel(const float* __restrict__ F) {
    int gw = (blockIdx.x * blockDim.x + threadIdx.x) >> 5;
    int lane = threadIdx.x & 31;
    if (gw >= NTOT) return;
    float4 v = reinterpret_cast<const float4*>(F + (size_t)gw * DIMK)[lane];
    float s = v.x * v.x + v.y * v.y + v.z * v.z + v.w * v.w;
    #pragma unroll
    for (int o = 16; o > 0; o >>= 1) s += __shfl_xor_sync(0xffffffffu, s, o);
    if (lane == 0) g_norm[gw] = s;
}

// Exact fp32 alignment term: sum_i log(1 + |a_i-b_i|^2), one warp per i.
__global__ void align_kernel(const float* __restrict__ F) {
    int gw = (blockIdx.x * blockDim.x + threadIdx.x) >> 5;
    int lane = threadIdx.x & 31;
    int wid = threadIdx.x >> 5;
    __shared__ float sh[8];
    float part = 0.f;
    if (gw < NHALF) {
        float4 a = reinterpret_cast<const float4*>(F + (size_t)gw * DIMK)[lane];
        float4 b = reinterpret_cast<const float4*>(F + (size_t)(gw + NHALF) * DIMK)[lane];
        float dx = a.x - b.x, dy = a.y - b.y, dz = a.z - b.z, dw = a.w - b.w;
        float s = dx * dx + dy * dy + dz * dz + dw * dw;
        #pragma unroll
        for (int o = 16; o > 0; o >>= 1) s += __shfl_xor_sync(0xffffffffu, s, o);
        if (lane == 0) part = logf(1.f + s);
    }
    if (lane == 0) sh[wid] = part;
    __syncthreads();
    if (threadIdx.x == 0) {
        float t = 0.f;
        #pragma unroll
        for (int i = 0; i < 8; i++) t += sh[i];
        atomicAdd(&g_alignneg, t);
    }
}

// ---------------- main tile kernel (mma.sync tf32) ----------------
// CTA = 128x128 tile of quadrant q (0=aa, 1=bb, 2=ab); 8 warps in a 2x4
// grid, each warp owns a 64x32 sub-tile. aa/bb upper-triangle only with
// mirrored col-sum scatter. K is split in two 64-chunks, double-buffered
// through cp.async.
#define KCH   64
#define LDS_S 68            // 64 + 4 pad: conflict-free fragment LDS
#define BUFFLT (128 * LDS_S)

__global__ void __launch_bounds__(256, 1) pair_mma_kernel(const float* __restrict__ F) {
    const int q = blockIdx.z, ti = blockIdx.y, tj = blockIdx.x;
    if (q < 2 && tj < ti) return;

    extern __shared__ float sm[];
    __shared__ float sh_ni[128], sh_nj[128];
    __shared__ float rowAcc[128][4];
    __shared__ float colAcc[128][2];

    const int tid = threadIdx.x;
    const int wid = tid >> 5, lane = tid & 31;
    const int g = lane >> 2, t = lane & 3;
    const int rowOff = (wid >> 2) * 64;       // warpRow
    const int colOff = (wid & 3) * 32;        // warpCol

    const int iBase = ((q == 1) ? NHALF : 0) + ti * 128;
    const int jBase = ((q == 0) ? 0 : NHALF) + tj * 128;

    float* Abuf[2] = { sm,              sm + BUFFLT };
    float* Bbuf[2] = { sm + 2 * BUFFLT, sm + 3 * BUFFLT };

    // ---- issue async loads for both 64-wide K chunks ----
    #pragma unroll
    for (int c = 0; c < 2; c++) {
        #pragma unroll
        for (int i = 0; i < 8; i++) {
            int f = tid + i * 256;            // 2048 float4 per matrix-chunk
            int row = f >> 4, c4 = f & 15;
            const float* gA = F + (size_t)(iBase + row) * DIMK + c * KCH + c4 * 4;
            const float* gB = F + (size_t)(jBase + row) * DIMK + c * KCH + c4 * 4;
            uint32_t sA = s2u(Abuf[c] + row * LDS_S + c4 * 4);
            uint32_t sB = s2u(Bbuf[c] + row * LDS_S + c4 * 4);
            asm volatile("cp.async.cg.shared.global [%0], [%1], 16;" :: "r"(sA), "l"(gA));
            asm volatile("cp.async.cg.shared.global [%0], [%1], 16;" :: "r"(sB), "l"(gB));
        }
        asm volatile("cp.async.commit_group;" ::: "memory");
    }

    if (tid < 128) sh_ni[tid] = g_norm[iBase + tid];
    else           sh_nj[tid - 128] = g_norm[jBase + tid - 128];

    float acc[4][4][4];
    #pragma unroll
    for (int mt = 0; mt < 4; mt++)
        #pragma unroll
        for (int nt = 0; nt < 4; nt++)
            #pragma unroll
            for (int e = 0; e < 4; e++) acc[mt][nt][e] = 0.f;

    // ---- compute chunks ----
    #pragma unroll
    for (int c = 0; c < 2; c++) {
        if (c == 0) asm volatile("cp.async.wait_group 1;" ::: "memory");
        else        asm volatile("cp.async.wait_group 0;" ::: "memory");
        __syncthreads();
        const float* A = Abuf[c];
        const float* B = Bbuf[c];
        #pragma unroll
        for (int ks = 0; ks < 8; ks++) {
            const int k0 = ks * 8;
            uint32_t af[4][4], bf[4][2];
            #pragma unroll
            for (int mt = 0; mt < 4; mt++) {
                const float* pa = A + (rowOff + mt * 16 + g) * LDS_S + k0 + t;
                af[mt][0] = __float_as_uint(pa[0]);
                af[mt][1] = __float_as_uint(pa[8 * LDS_S]);
                af[mt][2] = __float_as_uint(pa[4]);
                af[mt][3] = __float_as_uint(pa[8 * LDS_S + 4]);
            }
            #pragma unroll
            for (int nt = 0; nt < 4; nt++) {
                const float* pb = B + (colOff + nt * 8 + g) * LDS_S + k0 + t;
                bf[nt][0] = __float_as_uint(pb[0]);
                bf[nt][1] = __float_as_uint(pb[4]);
            }
            #pragma unroll
            for (int mt = 0; mt < 4; mt++)
                #pragma unroll
                for (int nt = 0; nt < 4; nt++)
                    mma_tf32(acc[mt][nt], af[mt], bf[nt]);
        }
        __syncthreads();
    }

    // ---- epilogue: dot -> Cauchy sim, warp-shuffle reductions ----
    float rn[8], cn[8];
    #pragma unroll
    for (int mt = 0; mt < 4; mt++) {
        rn[mt * 2 + 0] = sh_ni[rowOff + mt * 16 + g];
        rn[mt * 2 + 1] = sh_ni[rowOff + mt * 16 + g + 8];
    }
    #pragma unroll
    for (int nt = 0; nt < 4; nt++) {
        cn[nt * 2 + 0] = sh_nj[colOff + nt * 8 + 2 * t];
        cn[nt * 2 + 1] = sh_nj[colOff + nt * 8 + 2 * t + 1];
    }

    const bool dz = (q < 2) && (ti == tj);
    float rowsum[8], colsum[8];
    #pragma unroll
    for (int i = 0; i < 8; i++) { rowsum[i] = 0.f; colsum[i] = 0.f; }

    #pragma unroll
    for (int mt = 0; mt < 4; mt++)
        #pragma unroll
        for (int nt = 0; nt < 4; nt++)
            #pragma unroll
            for (int e = 0; e < 4; e++) {
                const int h = e >> 1, p = e & 1;
                float d2 = fmaxf(fmaf(-2.f, acc[mt][nt][e],
                                      rn[mt * 2 + h] + cn[nt * 2 + p]), 0.f);
                float sim = __fdividef(1.f, d2 + 1.f);
                if (dz && (rowOff + mt * 16 + g + h * 8) ==
                          (colOff + nt * 8 + 2 * t + p)) sim = 0.f;
                rowsum[mt * 2 + h] += sim;
                colsum[nt * 2 + p] += sim;
            }

    // row sums: reduce over the n-direction lanes (t = lane&3)
    #pragma unroll
    for (int i = 0; i < 8; i++) {
        rowsum[i] += __shfl_xor_sync(0xffffffffu, rowsum[i], 1);
        rowsum[i] += __shfl_xor_sync(0xffffffffu, rowsum[i], 2);
    }
    if (t == 0) {
        #pragma unroll
        for (int mt = 0; mt < 4; mt++) {
            rowAcc[rowOff + mt * 16 + g][wid & 3]     = rowsum[mt * 2 + 0];
            rowAcc[rowOff + mt * 16 + g + 8][wid & 3] = rowsum[mt * 2 + 1];
        }
    }
    // col sums: reduce over the m-direction lanes (g = lane>>2)
    #pragma unroll
    for (int i = 0; i < 8; i++) {
        colsum[i] += __shfl_xor_sync(0xffffffffu, colsum[i], 4);
        colsum[i] += __shfl_xor_sync(0xffffffffu, colsum[i], 8);
        colsum[i] += __shfl_xor_sync(0xffffffffu, colsum[i], 16);
    }
    if (g == 0) {
        #pragma unroll
        for (int nt = 0; nt < 4; nt++) {
            colAcc[colOff + nt * 8 + 2 * t][wid >> 2]     = colsum[nt * 2 + 0];
            colAcc[colOff + nt * 8 + 2 * t + 1][wid >> 2] = colsum[nt * 2 + 1];
        }
    }
    __syncthreads();

    if (tid < 128) {
        float s = rowAcc[tid][0] + rowAcc[tid][1] + rowAcc[tid][2] + rowAcc[tid][3];
        float* dst = (q == 0) ? g_rowsum_aa : ((q == 1) ? g_rowsum_bb : g_rowsum_ab);
        atomicAdd(&dst[ti * 128 + tid], s);
    } else {
        int c = tid - 128;
        float s = colAcc[c][0] + colAcc[c][1];
        if (q == 2) {
            atomicAdd(&g_colsum_ab[tj * 128 + c], s);
        } else if (ti != tj) {    // symmetric mirror contribution
            atomicAdd((q == 0) ? &g_rowsum_aa[tj * 128 + c]
                               : &g_rowsum_bb[tj * 128 + c], s);
        }
    }
}

__global__ void finalize_kernel(float* __restrict__ out) {
    __shared__ float sh[256];
    float s = 0.f;
    for (int j = threadIdx.x; j < NHALF; j += 256) {
        s += logf(g_colsum_ab[j] + g_rowsum_bb[j]);   // logsumexp_1 terms
        s += logf(g_rowsum_aa[j] + g_rowsum_ab[j]);   // logsumexp_2 terms
    }
    sh[threadIdx.x] = s;
    __syncthreads();
    for (int o = 128; o > 0; o >>= 1) {
        if (threadIdx.x < o) sh[threadIdx.x] += sh[threadIdx.x + o];
        __syncthreads();
    }
    if (threadIdx.x == 0) {
        float uniformity = sh[0] / (float)NHALF;
        float alignment = -g_alignneg / (float)NHALF;
        out[0] = -(alignment - 0.5f * uniformity);
    }
}

// ---------------- launch ----------------
extern "C" void kernel_launch(void* const* d_in, const int* in_sizes, int n_in,
                              void* d_out, int out_size) {
    const float* F = (const float*)d_in[0];
    float* out = (float*)d_out;

    const int SMEM_BYTES = 4 * BUFFLT * 4;   // 139264
    cudaFuncSetAttribute(pair_mma_kernel,
                         cudaFuncAttributeMaxDynamicSharedMemorySize, SMEM_BYTES);

    zero_kernel<<<(NHALF + 255) / 256, 256>>>();
    norm_kernel<<<(NTOT * 32) / 256, 256>>>(F);
    align_kernel<<<(NHALF * 32) / 256, 256>>>(F);
    dim3 grid(64, 64, 3);
    pair_mma_kernel<<<grid, 256, SMEM_BYTES>>>(F);
    finalize_kernel<<<1, 256>>>(out);
}

// round 4
// speedup vs baseline: 6.0206x; 2.1366x over previous
#include <cuda_runtime.h>
#include <cuda_fp16.h>
#include <math.h>
#include <stdint.h>

#define NHALF 8192
#define NTOT  16384
#define DIMK  128

// ---------------- device scratch (allocation-free rule) ----------------
__device__ float g_norm[NTOT];
__device__ float g_rowsum_aa[NHALF];
__device__ float g_rowsum_bb[NHALF];
__device__ float g_rowsum_ab[NHALF];
__device__ float g_colsum_ab[NHALF];
__device__ float g_alignneg;                  // sum_i log(1+|a_i-b_i|^2), exact fp32
__device__ __half g_h[(size_t)NTOT * DIMK];   // fp16 copy of features (4 MB)

__device__ __forceinline__ uint32_t s2u(const void* p) {
    uint32_t r;
    asm("{ .reg .u64 t; cvta.to.shared.u64 t, %1; cvt.u32.u64 %0, t; }"
        : "=r"(r) : "l"(p));
    return r;
}

__device__ __forceinline__ void mma_fp16(float* d, const uint32_t* a, const uint32_t* b) {
    asm volatile(
        "mma.sync.aligned.m16n8k16.row.col.f32.f16.f16.f32 "
        "{%0,%1,%2,%3}, {%4,%5,%6,%7}, {%8,%9}, {%0,%1,%2,%3};"
        : "+f"(d[0]), "+f"(d[1]), "+f"(d[2]), "+f"(d[3])
        : "r"(a[0]), "r"(a[1]), "r"(a[2]), "r"(a[3]), "r"(b[0]), "r"(b[1]));
}

#define LDSM_X4(r0, r1, r2, r3, addr) \
    asm volatile("ldmatrix.sync.aligned.m8n8.x4.shared.b16 {%0,%1,%2,%3}, [%4];" \
                 : "=r"(r0), "=r"(r1), "=r"(r2), "=r"(r3) : "r"(addr))

// ---------------- setup kernels ----------------
__global__ void zero_kernel() {
    int i = blockIdx.x * blockDim.x + threadIdx.x;
    if (i < NHALF) {
        g_rowsum_aa[i] = 0.f; g_rowsum_bb[i] = 0.f;
        g_rowsum_ab[i] = 0.f; g_colsum_ab[i] = 0.f;
    }
    if (i == 0) g_alignneg = 0.f;
}

// One warp per row: convert fp32 -> fp16, store, and compute the norm of the
// ROUNDED vector (so d2 = ni+nj-2*dot is the exact distance of rounded data).
__global__ void convert_norm_kernel(const float* __restrict__ F) {
    int gw = (blockIdx.x * blockDim.x + threadIdx.x) >> 5;
    int lane = threadIdx.x & 31;
    if (gw >= NTOT) return;
    float4 v = reinterpret_cast<const float4*>(F + (size_t)gw * DIMK)[lane];
    __half2 h0 = __floats2half2_rn(v.x, v.y);
    __half2 h1 = __floats2half2_rn(v.z, v.w);
    __half2* dst = reinterpret_cast<__half2*>(g_h + (size_t)gw * DIMK);
    dst[lane * 2 + 0] = h0;
    dst[lane * 2 + 1] = h1;
    float2 c0 = __half22float2(h0), c1 = __half22float2(h1);
    float s = c0.x * c0.x + c0.y * c0.y + c1.x * c1.x + c1.y * c1.y;
    #pragma unroll
    for (int o = 16; o > 0; o >>= 1) s += __shfl_xor_sync(0xffffffffu, s, o);
    if (lane == 0) g_norm[gw] = s;
}

// Exact fp32 alignment term: sum_i log(1 + |a_i-b_i|^2), one warp per i.
__global__ void align_kernel(const float* __restrict__ F) {
    int gw = (blockIdx.x * blockDim.x + threadIdx.x) >> 5;
    int lane = threadIdx.x & 31;
    int wid = threadIdx.x >> 5;
    __shared__ float sh[8];
    float part = 0.f;
    if (gw < NHALF) {
        float4 a = reinterpret_cast<const float4*>(F + (size_t)gw * DIMK)[lane];
        float4 b = reinterpret_cast<const float4*>(F + (size_t)(gw + NHALF) * DIMK)[lane];
        float dx = a.x - b.x, dy = a.y - b.y, dz = a.z - b.z, dw = a.w - b.w;
        float s = dx * dx + dy * dy + dz * dz + dw * dw;
        #pragma unroll
        for (int o = 16; o > 0; o >>= 1) s += __shfl_xor_sync(0xffffffffu, s, o);
        if (lane == 0) part = logf(1.f + s);
    }
    if (lane == 0) sh[wid] = part;
    __syncthreads();
    if (threadIdx.x == 0) {
        float t = 0.f;
        #pragma unroll
        for (int i = 0; i < 8; i++) t += sh[i];
        atomicAdd(&g_alignneg, t);
    }
}

// ---------------- main tile kernel (fp16 mma + ldmatrix) ----------------
// CTA = 128x128 tile of quadrant q (0=aa, 1=bb, 2=ab); 8 warps (2x4), each
// owns a 64x32 sub-tile. Smem layout per matrix: row stride 256 B (128 fp16);
// 16 B chunk kc of row r lives at r*256 + ((kc ^ (r&7)) << 4)  -> conflict-free
// for both cp.async fills and ldmatrix reads.
__global__ void __launch_bounds__(256, 2) pair_mma_kernel() {
    const int q = blockIdx.z, ti = blockIdx.y, tj = blockIdx.x;
    if (q < 2 && tj < ti) return;

    extern __shared__ char sm[];
    __shared__ float sh_ni[128], sh_nj[128];
    __shared__ float rowAcc[128][4];
    __shared__ float colAcc[128][2];

    const int tid = threadIdx.x;
    const int wid = tid >> 5, lane = tid & 31;
    const int g = lane >> 2, t = lane & 3;
    const int rowOff = (wid >> 2) * 64;        // warp row (2 groups of 64)
    const int colOff = (wid & 3) * 32;         // warp col (4 groups of 32)

    const int iBase = ((q == 1) ? NHALF : 0) + ti * 128;
    const int jBase = ((q == 0) ? 0 : NHALF) + tj * 128;

    const uint32_t smbase = s2u(sm);

    // ---- async fill: 4096 x 16B chunks (A then B) ----
    #pragma unroll
    for (int it = 0; it < 16; it++) {
        int c = tid + it * 256;
        int mat = c >> 11;                 // 0 = A, 1 = B
        int r = (c >> 4) & 127;
        int kc = c & 15;
        const __half* gp = g_h + (size_t)((mat ? jBase : iBase) + r) * DIMK + kc * 8;
        uint32_t dst = smbase + mat * 32768 + r * 256 + (((kc ^ (r & 7))) << 4);
        asm volatile("cp.async.cg.shared.global [%0], [%1], 16;" :: "r"(dst), "l"(gp));
    }
    asm volatile("cp.async.commit_group;" ::: "memory");

    if (tid < 128) sh_ni[tid] = g_norm[iBase + tid];
    else           sh_nj[tid - 128] = g_norm[jBase + tid - 128];

    float acc[4][4][4];
    #pragma unroll
    for (int mt = 0; mt < 4; mt++)
        #pragma unroll
        for (int nt = 0; nt < 4; nt++)
            #pragma unroll
            for (int e = 0; e < 4; e++) acc[mt][nt][e] = 0.f;

    // Per-lane ldmatrix base addresses (row part is ks-invariant).
    uint32_t aBase[4], bBase[2];
    int rsA[4], rsB[2];
    const int kbA = lane >> 4;                   // k-half for A matrices 2,3
    const int kbB = (lane >> 3) & 1;             // k-half for B matrices 1,3
    #pragma unroll
    for (int mt = 0; mt < 4; mt++) {
        int row = rowOff + mt * 16 + (lane & 7) + ((lane >> 3) & 1) * 8;
        aBase[mt] = smbase + row * 256;
        rsA[mt] = row & 7;
    }
    #pragma unroll
    for (int bt = 0; bt < 2; bt++) {
        int nrow = colOff + bt * 16 + ((lane >> 4) * 8) + (lane & 7);
        bBase[bt] = smbase + 32768 + nrow * 256;
        rsB[bt] = nrow & 7;
    }

    asm volatile("cp.async.wait_group 0;" ::: "memory");
    __syncthreads();

    // ---- MMA mainloop: 8 ksteps of K=16 ----
    #pragma unroll
    for (int ks = 0; ks < 8; ks++) {
        uint32_t af[4][4], bf[4][2];
        #pragma unroll
        for (int mt = 0; mt < 4; mt++) {
            uint32_t addr = aBase[mt] + ((((2 * ks + kbA) ^ rsA[mt])) << 4);
            LDSM_X4(af[mt][0], af[mt][1], af[mt][2], af[mt][3], addr);
        }
        #pragma unroll
        for (int bt = 0; bt < 2; bt++) {
            uint32_t addr = bBase[bt] + ((((2 * ks + kbB) ^ rsB[bt])) << 4);
            LDSM_X4(bf[bt * 2][0], bf[bt * 2][1], bf[bt * 2 + 1][0], bf[bt * 2 + 1][1], addr);
        }
        #pragma unroll
        for (int mt = 0; mt < 4; mt++)
            #pragma unroll
            for (int nt = 0; nt < 4; nt++)
                mma_fp16(acc[mt][nt], af[mt], bf[nt]);
    }

    // ---- epilogue: dot -> Cauchy sim, warp-shuffle reductions ----
    float rn[8], cn[8];
    #pragma unroll
    for (int mt = 0; mt < 4; mt++) {
        rn[mt * 2 + 0] = sh_ni[rowOff + mt * 16 + g];
        rn[mt * 2 + 1] = sh_ni[rowOff + mt * 16 + g + 8];
    }
    #pragma unroll
    for (int nt = 0; nt < 4; nt++) {
        cn[nt * 2 + 0] = sh_nj[colOff + nt * 8 + 2 * t];
        cn[nt * 2 + 1] = sh_nj[colOff + nt * 8 + 2 * t + 1];
    }

    const bool dz = (q < 2) && (ti == tj);
    float rowsum[8], colsum[8];
    #pragma unroll
    for (int i = 0; i < 8; i++) { rowsum[i] = 0.f; colsum[i] = 0.f; }

    #pragma unroll
    for (int mt = 0; mt < 4; mt++)
        #pragma unroll
        for (int nt = 0; nt < 4; nt++)
            #pragma unroll
            for (int e = 0; e < 4; e++) {
                const int h = e >> 1, p = e & 1;
                float d2 = fmaxf(fmaf(-2.f, acc[mt][nt][e],
                                      rn[mt * 2 + h] + cn[nt * 2 + p]), 0.f);
                float sim = __fdividef(1.f, d2 + 1.f);
                if (dz && (rowOff + mt * 16 + g + h * 8) ==
                          (colOff + nt * 8 + 2 * t + p)) sim = 0.f;
                rowsum[mt * 2 + h] += sim;
                colsum[nt * 2 + p] += sim;
            }

    // row sums: reduce across n-direction lanes (t)
    #pragma unroll
    for (int i = 0; i < 8; i++) {
        rowsum[i] += __shfl_xor_sync(0xffffffffu, rowsum[i], 1);
        rowsum[i] += __shfl_xor_sync(0xffffffffu, rowsum[i], 2);
    }
    if (t == 0) {
        #pragma unroll
        for (int mt = 0; mt < 4; mt++) {
            rowAcc[rowOff + mt * 16 + g][wid & 3]     = rowsum[mt * 2 + 0];
            rowAcc[rowOff + mt * 16 + g + 8][wid & 3] = rowsum[mt * 2 + 1];
        }
    }
    // col sums: reduce across m-direction lanes (g)
    #pragma unroll
    for (int i = 0; i < 8; i++) {
        colsum[i] += __shfl_xor_sync(0xffffffffu, colsum[i], 4);
        colsum[i] += __shfl_xor_sync(0xffffffffu, colsum[i], 8);
        colsum[i] += __shfl_xor_sync(0xffffffffu, colsum[i], 16);
    }
    if (g == 0) {
        #pragma unroll
        for (int nt = 0; nt < 4; nt++) {
            colAcc[colOff + nt * 8 + 2 * t][wid >> 2]     = colsum[nt * 2 + 0];
            colAcc[colOff + nt * 8 + 2 * t + 1][wid >> 2] = colsum[nt * 2 + 1];
        }
    }
    __syncthreads();

    if (tid < 128) {
        float s = rowAcc[tid][0] + rowAcc[tid][1] + rowAcc[tid][2] + rowAcc[tid][3];
        float* dst = (q == 0) ? g_rowsum_aa : ((q == 1) ? g_rowsum_bb : g_rowsum_ab);
        atomicAdd(&dst[ti * 128 + tid], s);
    } else {
        int c = tid - 128;
        float s = colAcc[c][0] + colAcc[c][1];
        if (q == 2) {
            atomicAdd(&g_colsum_ab[tj * 128 + c], s);
        } else if (ti != tj) {    // symmetric mirror contribution
            atomicAdd((q == 0) ? &g_rowsum_aa[tj * 128 + c]
                               : &g_rowsum_bb[tj * 128 + c], s);
        }
    }
}

__global__ void finalize_kernel(float* __restrict__ out) {
    __shared__ float sh[256];
    float s = 0.f;
    for (int j = threadIdx.x; j < NHALF; j += 256) {
        s += logf(g_colsum_ab[j] + g_rowsum_bb[j]);   // logsumexp_1 terms
        s += logf(g_rowsum_aa[j] + g_rowsum_ab[j]);   // logsumexp_2 terms
    }
    sh[threadIdx.x] = s;
    __syncthreads();
    for (int o = 128; o > 0; o >>= 1) {
        if (threadIdx.x < o) sh[threadIdx.x] += sh[threadIdx.x + o];
        __syncthreads();
    }
    if (threadIdx.x == 0) {
        float uniformity = sh[0] / (float)NHALF;
        float alignment = -g_alignneg / (float)NHALF;
        out[0] = -(alignment - 0.5f * uniformity);
    }
}

// ---------------- launch ----------------
extern "C" void kernel_launch(void* const* d_in, const int* in_sizes, int n_in,
                              void* d_out, int out_size) {
    const float* F = (const float*)d_in[0];
    float* out = (float*)d_out;

    const int SMEM_BYTES = 65536;     // A(32KB) + B(32KB) fp16
    cudaFuncSetAttribute(pair_mma_kernel,
                         cudaFuncAttributeMaxDynamicSharedMemorySize, SMEM_BYTES);

    zero_kernel<<<(NHALF + 255) / 256, 256>>>();
    convert_norm_kernel<<<(NTOT * 32) / 256, 256>>>(F);
    align_kernel<<<(NHALF * 32) / 256, 256>>>(F);
    dim3 grid(64, 64, 3);
    pair_mma_kernel<<<grid, 256, SMEM_BYTES>>>();
    finalize_kernel<<<1, 256>>>(out);
}